// round 11
// baseline (speedup 1.0000x reference)
#include <cuda_runtime.h>
#include <stdint.h>

#define Bn 16384
#define Tn 256
#define Dn 8
#define Fn 512
#define Cn 16
#define Ln 256

#define TTILES 16            // tree tiles (16 trees each)
#define TPT    (Tn / TTILES)
#define BTILES 16            // sample tiles (1024 samples each)
#define BTILE  1024

// ---------------- device scratch (static, no runtime allocation) ------------
__device__ unsigned short g_fidx16[Tn * Dn];   // TRANSFORMED offsets (see k_argmax)
__device__ unsigned char  g_dec[(size_t)Tn * Bn];            // 4 MB, layout [T][B]
__device__ float          g_part[(size_t)TTILES * Bn * Cn];  // 16 MB partials
__device__ int            g_scratch[16];

// ---------------- kernel 1: argmax over F per (tree, depth) -----------------
// stores the smem-layout-transformed offset (f&3)*128 + (f>>2) so k_decide's
// gather needs no per-access remap arithmetic.
__global__ void k_argmax(const float* __restrict__ fw) {
    int g    = blockIdx.x * 8 + (threadIdx.x >> 5);   // 2048 warps total
    int lane = threadIdx.x & 31;
    const float* p = fw + (size_t)g * Fn;

    float v[16];
    #pragma unroll
    for (int i = 0; i < 16; i++) v[i] = p[lane + (i << 5)];

    float best = v[0];
    int   bi   = lane;
    #pragma unroll
    for (int i = 1; i < 16; i++)
        if (v[i] > best) { best = v[i]; bi = lane + (i << 5); }

    #pragma unroll
    for (int off = 16; off; off >>= 1) {
        float ov = __shfl_down_sync(0xffffffffu, best, off);
        int   oi = __shfl_down_sync(0xffffffffu, bi,   off);
        if (ov > best || (ov == best && oi < bi)) { best = ov; bi = oi; }
    }
    if (lane == 0)
        g_fidx16[g] = (unsigned short)(((bi & 3) << 7) + (bi >> 2));
}

// ---------------- kernel 2: per-(sample,tree) decision byte -----------------
// round-9 version (best measured). x rows in smem, stride 513, transposed
// within the row: addr(row,f) = 513*row + (f&3)*128 + (f>>2).
// Staging stores and gathers both bank-conflict-free. fidx/thr in smem.
__global__ __launch_bounds__(512) void k_decide(const float* __restrict__ x,
                                                const float* __restrict__ thr) {
    extern __shared__ float smem[];
    float* s_x   = smem;                                   // 32 * 513 floats
    uint4* s_fpk = (uint4*)(smem + 32 * 513);              // 256 * 16 B
    float* s_thr = (float*)(s_fpk + Tn);                   // 2048 floats

    int tid = threadIdx.x;
    int b0  = blockIdx.x * 32;

    const float4* xg = (const float4*)x + (size_t)b0 * (Fn / 4);
    for (int i = tid; i < 32 * (Fn / 4); i += 512) {
        float4 v = xg[i];
        int row = i >> 7, c4 = i & 127;
        float* dst = s_x + row * 513 + c4;      // k-th component at +128k
        dst[0]   = v.x;
        dst[128] = v.y;
        dst[256] = v.z;
        dst[384] = v.w;
    }
    for (int i = tid; i < (Tn * Dn) / 2; i += 512)
        ((unsigned*)s_fpk)[i] = ((const unsigned*)g_fidx16)[i];
    for (int i = tid; i < Tn * Dn; i += 512)
        s_thr[i] = thr[i];
    __syncthreads();

    int warp = tid >> 5, lane = tid & 31;
    const float* xr = s_x + lane * 513;

    #pragma unroll 4
    for (int tt = 0; tt < 16; tt++) {
        int t = warp * 16 + tt;
        uint4 fp = s_fpk[t];
        const float4* th = (const float4*)(s_thr + t * 8);
        float4 t0 = th[0], t1 = th[1];
        unsigned dec = 0;
        dec = (dec << 1) | (unsigned)(xr[fp.x & 0xFFFFu] > t0.x);
        dec = (dec << 1) | (unsigned)(xr[fp.x >> 16]     > t0.y);
        dec = (dec << 1) | (unsigned)(xr[fp.y & 0xFFFFu] > t0.z);
        dec = (dec << 1) | (unsigned)(xr[fp.y >> 16]     > t0.w);
        dec = (dec << 1) | (unsigned)(xr[fp.z & 0xFFFFu] > t1.x);
        dec = (dec << 1) | (unsigned)(xr[fp.z >> 16]     > t1.y);
        dec = (dec << 1) | (unsigned)(xr[fp.w & 0xFFFFu] > t1.z);
        dec = (dec << 1) | (unsigned)(xr[fp.w >> 16]     > t1.w);
        g_dec[(size_t)t * Bn + b0 + lane] = (unsigned char)dec;
    }
}

// ---------------- launch-slot shim -------------------------------------------
__global__ void k_tiny() { if (threadIdx.x < 16) g_scratch[threadIdx.x] = 0; }

// ---------------- kernel 3: cooperative leaf gather ---------------------------
// round-7 register-prefetch double buffer, now with __launch_bounds__(512,3):
// round-7 profile showed regs=64 -> 2 blocks/SM, occ 41% on an L1-latency
// exposed loop. 42-reg cap -> 3 blocks/SM (+50% warps). Accumulators (32 regs)
// + indices fit; only rematerialization expected, no hot-loop spills.
__global__ __launch_bounds__(512, 3) void k_accum(const float* __restrict__ resp) {
    extern __shared__ float4 dynsmem[];
    float4*   s_r  = dynsmem;                            // 2 * Ln*4 float4
    unsigned* s_du = (unsigned*)(dynsmem + 2 * Ln * 4);  // 2 * 256 u32

    int tid   = threadIdx.x;
    int w     = tid >> 5;
    int l     = tid & 31;
    int q     = l & 3;
    int sg    = l >> 2;
    int sbase = w * 64 + sg * 8;          // this thread's first sample (local)
    int b0    = blockIdx.x * BTILE;
    int tbase = blockIdx.y * TPT;

    float4 a[8];
    #pragma unroll
    for (int i = 0; i < 8; i++) a[i] = make_float4(0.f, 0.f, 0.f, 0.f);

    {
        const float4* rs = (const float4*)resp + (size_t)tbase * (Ln * Cn / 4);
        #pragma unroll
        for (int j = 0; j < 2; j++) {
            int i = tid + j * 512;
            float4 v = rs[i];
            int d = i >> 2, k = i & 3;
            s_r[d * 4 + ((k + (d >> 1)) & 3)] = v;
        }
        if (tid < BTILE / 4)
            s_du[tid] = ((const unsigned*)(g_dec + (size_t)tbase * Bn + b0))[tid];
    }
    __syncthreads();

    for (int tt = 0; tt < TPT; tt++) {
        int cur = tt & 1;
        float4 nv0, nv1; unsigned ndu = 0;
        bool have = (tt + 1 < TPT);
        if (have) {
            int t = tbase + tt + 1;
            const float4* rs = (const float4*)resp + (size_t)t * (Ln * Cn / 4);
            nv0 = rs[tid];
            nv1 = rs[tid + 512];
            if (tid < BTILE / 4)
                ndu = ((const unsigned*)(g_dec + (size_t)t * Bn + b0))[tid];
        }

        const float4* sr = s_r + cur * (Ln * 4);
        uint2 dw = *(const uint2*)((const unsigned char*)(s_du + cur * (BTILE / 4))
                                   + sbase);
        #pragma unroll
        for (int i = 0; i < 4; i++) {
            int d = (dw.x >> (8 * i)) & 255;
            float4 v = sr[d * 4 + ((q + (d >> 1)) & 3)];
            a[i].x += v.x; a[i].y += v.y; a[i].z += v.z; a[i].w += v.w;
        }
        #pragma unroll
        for (int i = 0; i < 4; i++) {
            int d = (dw.y >> (8 * i)) & 255;
            float4 v = sr[d * 4 + ((q + (d >> 1)) & 3)];
            a[4 + i].x += v.x; a[4 + i].y += v.y;
            a[4 + i].z += v.z; a[4 + i].w += v.w;
        }

        if (have) {
            int nb = cur ^ 1;
            float4* dr = s_r + nb * (Ln * 4);
            { int i = tid;       int d = i >> 2, k = i & 3; dr[d * 4 + ((k + (d >> 1)) & 3)] = nv0; }
            { int i = tid + 512; int d = i >> 2, k = i & 3; dr[d * 4 + ((k + (d >> 1)) & 3)] = nv1; }
            if (tid < BTILE / 4) s_du[nb * (BTILE / 4) + tid] = ndu;
        }
        __syncthreads();
    }

    float4* pb = (float4*)g_part + ((size_t)blockIdx.y * Bn + b0 + sbase) * 4 + q;
    #pragma unroll
    for (int i = 0; i < 8; i++) pb[i * 4] = a[i];
}

// ---------------- kernel 4: reduce 16 partial tiles --------------------------
__global__ __launch_bounds__(256) void k_reduce(float* __restrict__ out) {
    int i = blockIdx.x * 256 + threadIdx.x;       // float2 index
    const float2* p = (const float2*)g_part;
    const size_t S = (size_t)Bn * Cn / 2;         // tile stride in float2

    float2 c[8];
    #pragma unroll
    for (int j = 0; j < 8; j++) c[j] = make_float2(0.f, 0.f);

    #pragma unroll
    for (int m = 0; m < TTILES / 8; m++) {
        #pragma unroll
        for (int j = 0; j < 8; j++) {
            float2 v = p[(size_t)(m * 8 + j) * S + i];
            c[j].x += v.x; c[j].y += v.y;
        }
    }
    float sx = ((c[0].x + c[1].x) + (c[2].x + c[3].x)) +
               ((c[4].x + c[5].x) + (c[6].x + c[7].x));
    float sy = ((c[0].y + c[1].y) + (c[2].y + c[3].y)) +
               ((c[4].y + c[5].y) + (c[6].y + c[7].y));
    const float sc = 1.0f / (float)Tn;
    ((float2*)out)[i] = make_float2(sx * sc, sy * sc);
}

// ---------------- launch -----------------------------------------------------
extern "C" void kernel_launch(void* const* d_in, const int* in_sizes, int n_in,
                              void* d_out, int out_size) {
    const float* x    = (const float*)d_in[0];   // (B, F)
    const float* fw   = (const float*)d_in[1];   // (T, D, F)
    const float* thr  = (const float*)d_in[2];   // (T, D)
    const float* resp = (const float*)d_in[3];   // (T, L, C)
    float* out = (float*)d_out;                  // (B, C)

    const int smem_dec = 32 * 513 * 4 + Tn * 16 + Tn * Dn * 4;     // 77952 B
    const int smem_acc = 2 * Ln * 4 * 16 + 2 * (BTILE / 4) * 4;    // 34816 B
    cudaFuncSetAttribute(k_decide, cudaFuncAttributeMaxDynamicSharedMemorySize,
                         smem_dec);
    cudaFuncSetAttribute(k_accum, cudaFuncAttributeMaxDynamicSharedMemorySize,
                         smem_acc);
    (void)in_sizes; (void)n_in; (void)out_size;

    k_argmax<<<(Tn * Dn) / 8, 256>>>(fw);                      // launch 1
    k_decide<<<Bn / 32, 512, smem_dec>>>(x, thr);              // launch 2
    k_tiny<<<1, 32>>>();                                       // launch 3 (shim)
    k_accum<<<dim3(BTILES, TTILES), 512, smem_acc>>>(resp);    // launch 4 <- ncu
    k_reduce<<<(Bn * Cn / 2) / 256, 256>>>(out);               // launch 5
}

// round 12
// speedup vs baseline: 1.4780x; 1.4780x over previous
#include <cuda_runtime.h>
#include <stdint.h>

#define Bn 16384
#define Tn 256
#define Dn 8
#define Fn 512
#define Cn 16
#define Ln 256

#define TTILES 16            // tree tiles (16 trees each)
#define TPT    (Tn / TTILES)
#define BTILES 16            // sample tiles (1024 samples each)
#define BTILE  1024

// ---------------- device scratch (static, no runtime allocation) ------------
__device__ unsigned short g_fidx16[Tn * Dn];   // TRANSFORMED offsets (see k_argmax)
__device__ unsigned char  g_dec[(size_t)Tn * Bn];            // 4 MB, layout [T][B]
__device__ float          g_part[(size_t)TTILES * Bn * Cn];  // 16 MB partials
__device__ int            g_scratch[16];

// ---------------- kernel 1: argmax over F per (tree, depth) -----------------
// stores the smem-layout-transformed offset (f&3)*128 + (f>>2) so k_decide's
// gather needs no per-access remap arithmetic.
__global__ void k_argmax(const float* __restrict__ fw) {
    int g    = blockIdx.x * 8 + (threadIdx.x >> 5);   // 2048 warps total
    int lane = threadIdx.x & 31;
    const float* p = fw + (size_t)g * Fn;

    float v[16];
    #pragma unroll
    for (int i = 0; i < 16; i++) v[i] = p[lane + (i << 5)];

    float best = v[0];
    int   bi   = lane;
    #pragma unroll
    for (int i = 1; i < 16; i++)
        if (v[i] > best) { best = v[i]; bi = lane + (i << 5); }

    #pragma unroll
    for (int off = 16; off; off >>= 1) {
        float ov = __shfl_down_sync(0xffffffffu, best, off);
        int   oi = __shfl_down_sync(0xffffffffu, bi,   off);
        if (ov > best || (ov == best && oi < bi)) { best = ov; bi = oi; }
    }
    if (lane == 0)
        g_fidx16[g] = (unsigned short)(((bi & 3) << 7) + (bi >> 2));
}

// ---------------- kernel 2: per-(sample,tree) decision byte -----------------
// x rows in smem, stride 513, transposed within the row:
//   addr(row,f) = 513*row + (f&3)*128 + (f>>2)   (stores + gathers conflict-free)
// Compares are SIGN-BIT ARITHMETIC, not predicates: bit = sign(t - x).
// FSETP->@P has 13-cyc pred latency; FADD+SHR is 4+4 and fully pipelined —
// round-10 profile showed decide latency-bound (issue 48% at occ 64%).
__global__ __launch_bounds__(512) void k_decide(const float* __restrict__ x,
                                                const float* __restrict__ thr) {
    extern __shared__ float smem[];
    float* s_x   = smem;                                   // 32 * 513 floats
    uint4* s_fpk = (uint4*)(smem + 32 * 513);              // 256 * 16 B
    float* s_thr = (float*)(s_fpk + Tn);                   // 2048 floats

    int tid = threadIdx.x;
    int b0  = blockIdx.x * 32;

    const float4* xg = (const float4*)x + (size_t)b0 * (Fn / 4);
    for (int i = tid; i < 32 * (Fn / 4); i += 512) {
        float4 v = xg[i];
        int row = i >> 7, c4 = i & 127;
        float* dst = s_x + row * 513 + c4;      // k-th component at +128k
        dst[0]   = v.x;
        dst[128] = v.y;
        dst[256] = v.z;
        dst[384] = v.w;
    }
    for (int i = tid; i < (Tn * Dn) / 2; i += 512)
        ((unsigned*)s_fpk)[i] = ((const unsigned*)g_fidx16)[i];
    for (int i = tid; i < Tn * Dn; i += 512)
        s_thr[i] = thr[i];
    __syncthreads();

    int warp = tid >> 5, lane = tid & 31;
    const float* xr = s_x + lane * 513;

    #pragma unroll 4
    for (int tt = 0; tt < 16; tt++) {
        int t = warp * 16 + tt;
        uint4 fp = s_fpk[t];
        const float4* th = (const float4*)(s_thr + t * 8);
        float4 t0 = th[0], t1 = th[1];
        // batch all 8 gathers first (MLP), then branch-free sign-bit combine
        float x0 = xr[fp.x & 0xFFFFu];
        float x1 = xr[fp.x >> 16];
        float x2 = xr[fp.y & 0xFFFFu];
        float x3 = xr[fp.y >> 16];
        float x4 = xr[fp.z & 0xFFFFu];
        float x5 = xr[fp.z >> 16];
        float x6 = xr[fp.w & 0xFFFFu];
        float x7 = xr[fp.w >> 16];
        unsigned s0 = __float_as_uint(t0.x - x0) >> 31;   // (x > t) as 0/1
        unsigned s1 = __float_as_uint(t0.y - x1) >> 31;
        unsigned s2 = __float_as_uint(t0.z - x2) >> 31;
        unsigned s3 = __float_as_uint(t0.w - x3) >> 31;
        unsigned s4 = __float_as_uint(t1.x - x4) >> 31;
        unsigned s5 = __float_as_uint(t1.y - x5) >> 31;
        unsigned s6 = __float_as_uint(t1.z - x6) >> 31;
        unsigned s7 = __float_as_uint(t1.w - x7) >> 31;
        unsigned dec = (s0 << 7) | (s1 << 6) | (s2 << 5) | (s3 << 4) |
                       (s4 << 3) | (s5 << 2) | (s6 << 1) | s7;
        g_dec[(size_t)t * Bn + b0 + lane] = (unsigned char)dec;
    }
}

// ---------------- launch-slot shim -------------------------------------------
__global__ void k_tiny() { if (threadIdx.x < 16) g_scratch[threadIdx.x] = 0; }

// ---------------- kernel 3: cooperative leaf gather (round-9 exact) ----------
// register-prefetch double buffer, NO reg cap: launch_bounds(512,3) spilled
// to local (L2 7.8%->40.7%, 30->54 µs); cp.async slower twice. Closed topic.
__global__ __launch_bounds__(512) void k_accum(const float* __restrict__ resp) {
    extern __shared__ float4 dynsmem[];
    float4*   s_r  = dynsmem;                            // 2 * Ln*4 float4
    unsigned* s_du = (unsigned*)(dynsmem + 2 * Ln * 4);  // 2 * 256 u32

    int tid   = threadIdx.x;
    int w     = tid >> 5;
    int l     = tid & 31;
    int q     = l & 3;
    int sg    = l >> 2;
    int sbase = w * 64 + sg * 8;          // this thread's first sample (local)
    int b0    = blockIdx.x * BTILE;
    int tbase = blockIdx.y * TPT;

    float4 a[8];
    #pragma unroll
    for (int i = 0; i < 8; i++) a[i] = make_float4(0.f, 0.f, 0.f, 0.f);

    {
        const float4* rs = (const float4*)resp + (size_t)tbase * (Ln * Cn / 4);
        #pragma unroll
        for (int j = 0; j < 2; j++) {
            int i = tid + j * 512;
            float4 v = rs[i];
            int d = i >> 2, k = i & 3;
            s_r[d * 4 + ((k + (d >> 1)) & 3)] = v;
        }
        if (tid < BTILE / 4)
            s_du[tid] = ((const unsigned*)(g_dec + (size_t)tbase * Bn + b0))[tid];
    }
    __syncthreads();

    for (int tt = 0; tt < TPT; tt++) {
        int cur = tt & 1;
        float4 nv0, nv1; unsigned ndu = 0;
        bool have = (tt + 1 < TPT);
        if (have) {
            int t = tbase + tt + 1;
            const float4* rs = (const float4*)resp + (size_t)t * (Ln * Cn / 4);
            nv0 = rs[tid];
            nv1 = rs[tid + 512];
            if (tid < BTILE / 4)
                ndu = ((const unsigned*)(g_dec + (size_t)t * Bn + b0))[tid];
        }

        const float4* sr = s_r + cur * (Ln * 4);
        uint2 dw = *(const uint2*)((const unsigned char*)(s_du + cur * (BTILE / 4))
                                   + sbase);
        #pragma unroll
        for (int i = 0; i < 4; i++) {
            int d = (dw.x >> (8 * i)) & 255;
            float4 v = sr[d * 4 + ((q + (d >> 1)) & 3)];
            a[i].x += v.x; a[i].y += v.y; a[i].z += v.z; a[i].w += v.w;
        }
        #pragma unroll
        for (int i = 0; i < 4; i++) {
            int d = (dw.y >> (8 * i)) & 255;
            float4 v = sr[d * 4 + ((q + (d >> 1)) & 3)];
            a[4 + i].x += v.x; a[4 + i].y += v.y;
            a[4 + i].z += v.z; a[4 + i].w += v.w;
        }

        if (have) {
            int nb = cur ^ 1;
            float4* dr = s_r + nb * (Ln * 4);
            { int i = tid;       int d = i >> 2, k = i & 3; dr[d * 4 + ((k + (d >> 1)) & 3)] = nv0; }
            { int i = tid + 512; int d = i >> 2, k = i & 3; dr[d * 4 + ((k + (d >> 1)) & 3)] = nv1; }
            if (tid < BTILE / 4) s_du[nb * (BTILE / 4) + tid] = ndu;
        }
        __syncthreads();
    }

    float4* pb = (float4*)g_part + ((size_t)blockIdx.y * Bn + b0 + sbase) * 4 + q;
    #pragma unroll
    for (int i = 0; i < 8; i++) pb[i * 4] = a[i];
}

// ---------------- kernel 4: reduce 16 partial tiles --------------------------
__global__ __launch_bounds__(256) void k_reduce(float* __restrict__ out) {
    int i = blockIdx.x * 256 + threadIdx.x;       // float2 index
    const float2* p = (const float2*)g_part;
    const size_t S = (size_t)Bn * Cn / 2;         // tile stride in float2

    float2 c[8];
    #pragma unroll
    for (int j = 0; j < 8; j++) c[j] = make_float2(0.f, 0.f);

    #pragma unroll
    for (int m = 0; m < TTILES / 8; m++) {
        #pragma unroll
        for (int j = 0; j < 8; j++) {
            float2 v = p[(size_t)(m * 8 + j) * S + i];
            c[j].x += v.x; c[j].y += v.y;
        }
    }
    float sx = ((c[0].x + c[1].x) + (c[2].x + c[3].x)) +
               ((c[4].x + c[5].x) + (c[6].x + c[7].x));
    float sy = ((c[0].y + c[1].y) + (c[2].y + c[3].y)) +
               ((c[4].y + c[5].y) + (c[6].y + c[7].y));
    const float sc = 1.0f / (float)Tn;
    ((float2*)out)[i] = make_float2(sx * sc, sy * sc);
}

// ---------------- launch -----------------------------------------------------
extern "C" void kernel_launch(void* const* d_in, const int* in_sizes, int n_in,
                              void* d_out, int out_size) {
    const float* x    = (const float*)d_in[0];   // (B, F)
    const float* fw   = (const float*)d_in[1];   // (T, D, F)
    const float* thr  = (const float*)d_in[2];   // (T, D)
    const float* resp = (const float*)d_in[3];   // (T, L, C)
    float* out = (float*)d_out;                  // (B, C)

    const int smem_dec = 32 * 513 * 4 + Tn * 16 + Tn * Dn * 4;     // 77952 B
    const int smem_acc = 2 * Ln * 4 * 16 + 2 * (BTILE / 4) * 4;    // 34816 B
    cudaFuncSetAttribute(k_decide, cudaFuncAttributeMaxDynamicSharedMemorySize,
                         smem_dec);
    cudaFuncSetAttribute(k_accum, cudaFuncAttributeMaxDynamicSharedMemorySize,
                         smem_acc);
    (void)in_sizes; (void)n_in; (void)out_size;

    k_argmax<<<(Tn * Dn) / 8, 256>>>(fw);                      // launch 1
    k_tiny<<<1, 32>>>();                                       // launch 2 (shim)
    k_tiny<<<1, 32>>>();                                       // launch 3 (shim)
    k_decide<<<Bn / 32, 512, smem_dec>>>(x, thr);              // launch 4 <- ncu
    k_accum<<<dim3(BTILES, TTILES), 512, smem_acc>>>(resp);    // launch 5
    k_reduce<<<(Bn * Cn / 2) / 256, 256>>>(out);               // launch 6
}

// round 13
// speedup vs baseline: 1.5616x; 1.0566x over previous
#include <cuda_runtime.h>
#include <stdint.h>

#define Bn 16384
#define Tn 256
#define Dn 8
#define Fn 512
#define Cn 16
#define Ln 256

#define TTILES 16            // tree tiles (16 trees each)
#define TPT    (Tn / TTILES)
#define BTILES 16            // sample tiles (1024 samples each)
#define BTILE  1024

// ---------------- device scratch (static, no runtime allocation) ------------
__device__ unsigned short g_fidx16[Tn * Dn];   // PRE-SCALED byte offsets
__device__ unsigned char  g_dec[(size_t)Tn * Bn];            // 4 MB, layout [T][B]
__device__ float          g_part[(size_t)TTILES * Bn * Cn];  // 16 MB partials
__device__ int            g_scratch[16];

// ---------------- kernel 1: argmax over F per (tree, depth) -----------------
// stores the smem-layout-transformed offset as a BYTE offset:
//   ((f&3)*128 + (f>>2)) * 4   (max 2044, fits u16)
// so k_decide's gather is a direct byte-addressed LDS with no scale IMAD.
__global__ void k_argmax(const float* __restrict__ fw) {
    int g    = blockIdx.x * 8 + (threadIdx.x >> 5);   // 2048 warps total
    int lane = threadIdx.x & 31;
    const float* p = fw + (size_t)g * Fn;

    float v[16];
    #pragma unroll
    for (int i = 0; i < 16; i++) v[i] = p[lane + (i << 5)];

    float best = v[0];
    int   bi   = lane;
    #pragma unroll
    for (int i = 1; i < 16; i++)
        if (v[i] > best) { best = v[i]; bi = lane + (i << 5); }

    #pragma unroll
    for (int off = 16; off; off >>= 1) {
        float ov = __shfl_down_sync(0xffffffffu, best, off);
        int   oi = __shfl_down_sync(0xffffffffu, bi,   off);
        if (ov > best || (ov == best && oi < bi)) { best = ov; bi = oi; }
    }
    if (lane == 0)
        g_fidx16[g] = (unsigned short)((((bi & 3) << 7) + (bi >> 2)) << 2);
}

// ---------------- kernel 2: per-(sample,tree) decision byte -----------------
// x rows in smem, stride 513, transposed within the row (conflict-free both
// ways). Sign-bit compares (no predicates). Gather offsets are pre-scaled
// byte offsets -> LDS with zero address arithmetic beyond the add.
__global__ __launch_bounds__(512) void k_decide(const float* __restrict__ x,
                                                const float* __restrict__ thr) {
    extern __shared__ float smem[];
    float* s_x   = smem;                                   // 32 * 513 floats
    uint4* s_fpk = (uint4*)(smem + 32 * 513);              // 256 * 16 B
    float* s_thr = (float*)(s_fpk + Tn);                   // 2048 floats

    int tid = threadIdx.x;
    int b0  = blockIdx.x * 32;

    const float4* xg = (const float4*)x + (size_t)b0 * (Fn / 4);
    for (int i = tid; i < 32 * (Fn / 4); i += 512) {
        float4 v = xg[i];
        int row = i >> 7, c4 = i & 127;
        float* dst = s_x + row * 513 + c4;      // k-th component at +128k
        dst[0]   = v.x;
        dst[128] = v.y;
        dst[256] = v.z;
        dst[384] = v.w;
    }
    for (int i = tid; i < (Tn * Dn) / 2; i += 512)
        ((unsigned*)s_fpk)[i] = ((const unsigned*)g_fidx16)[i];
    for (int i = tid; i < Tn * Dn; i += 512)
        s_thr[i] = thr[i];
    __syncthreads();

    int warp = tid >> 5, lane = tid & 31;
    const char* xr = (const char*)(s_x + lane * 513);

    #pragma unroll 4
    for (int tt = 0; tt < 16; tt++) {
        int t = warp * 16 + tt;
        uint4 fp = s_fpk[t];
        const float4* th = (const float4*)(s_thr + t * 8);
        float4 t0 = th[0], t1 = th[1];
        float x0 = *(const float*)(xr + (fp.x & 0xFFFFu));
        float x1 = *(const float*)(xr + (fp.x >> 16));
        float x2 = *(const float*)(xr + (fp.y & 0xFFFFu));
        float x3 = *(const float*)(xr + (fp.y >> 16));
        float x4 = *(const float*)(xr + (fp.z & 0xFFFFu));
        float x5 = *(const float*)(xr + (fp.z >> 16));
        float x6 = *(const float*)(xr + (fp.w & 0xFFFFu));
        float x7 = *(const float*)(xr + (fp.w >> 16));
        unsigned s0 = __float_as_uint(t0.x - x0) >> 31;   // (x > t) as 0/1
        unsigned s1 = __float_as_uint(t0.y - x1) >> 31;
        unsigned s2 = __float_as_uint(t0.z - x2) >> 31;
        unsigned s3 = __float_as_uint(t0.w - x3) >> 31;
        unsigned s4 = __float_as_uint(t1.x - x4) >> 31;
        unsigned s5 = __float_as_uint(t1.y - x5) >> 31;
        unsigned s6 = __float_as_uint(t1.z - x6) >> 31;
        unsigned s7 = __float_as_uint(t1.w - x7) >> 31;
        unsigned dec = (s0 << 7) | (s1 << 6) | (s2 << 5) | (s3 << 4) |
                       (s4 << 3) | (s5 << 2) | (s6 << 1) | s7;
        g_dec[(size_t)t * Bn + b0 + lane] = (unsigned char)dec;
    }
}

// ---------------- launch-slot shim -------------------------------------------
__global__ void k_tiny() { if (threadIdx.x < 16) g_scratch[threadIdx.x] = 0; }

// ---------------- kernel 3: cooperative leaf gather, distance-2 prefetch -----
// Same layout/gather as round 9 (best measured). CHANGE: the LDG is issued at
// the BOTTOM of the iteration, AFTER the STS, and targets tree tt+2. The nv
// registers are dead between STS and LDG (no extra live range), smem stays
// double-buffered, but the LDG now has a full iteration of slack before its
// STS instead of one gather phase -> removes the per-iteration L2 latency
// exposure that kept accum ~2x above its pipe floor.
__global__ __launch_bounds__(512) void k_accum(const float* __restrict__ resp) {
    extern __shared__ float4 dynsmem[];
    float4*   s_r  = dynsmem;                            // 2 * Ln*4 float4
    unsigned* s_du = (unsigned*)(dynsmem + 2 * Ln * 4);  // 2 * 256 u32

    int tid   = threadIdx.x;
    int w     = tid >> 5;
    int l     = tid & 31;
    int q     = l & 3;
    int sg    = l >> 2;
    int sbase = w * 64 + sg * 8;          // this thread's first sample (local)
    int b0    = blockIdx.x * BTILE;
    int tbase = blockIdx.y * TPT;

    float4 a[8];
    #pragma unroll
    for (int i = 0; i < 8; i++) a[i] = make_float4(0.f, 0.f, 0.f, 0.f);

    float4 nv0, nv1; unsigned ndu = 0;

    // prologue: tree tbase -> buf0 (through regs), then LDG tree tbase+1 -> nv
    {
        const float4* rs = (const float4*)resp + (size_t)tbase * (Ln * Cn / 4);
        #pragma unroll
        for (int j = 0; j < 2; j++) {
            int i = tid + j * 512;
            float4 v = rs[i];
            int d = i >> 2, k = i & 3;
            s_r[d * 4 + ((k + (d >> 1)) & 3)] = v;
        }
        if (tid < BTILE / 4)
            s_du[tid] = ((const unsigned*)(g_dec + (size_t)tbase * Bn + b0))[tid];

        const float4* rs1 = (const float4*)resp + (size_t)(tbase + 1) * (Ln * Cn / 4);
        nv0 = rs1[tid];
        nv1 = rs1[tid + 512];
        if (tid < BTILE / 4)
            ndu = ((const unsigned*)(g_dec + (size_t)(tbase + 1) * Bn + b0))[tid];
    }
    __syncthreads();

    for (int tt = 0; tt < TPT; tt++) {
        int cur = tt & 1;

        const float4* sr = s_r + cur * (Ln * 4);
        uint2 dw = *(const uint2*)((const unsigned char*)(s_du + cur * (BTILE / 4))
                                   + sbase);
        #pragma unroll
        for (int i = 0; i < 4; i++) {
            int d = (dw.x >> (8 * i)) & 255;
            float4 v = sr[d * 4 + ((q + (d >> 1)) & 3)];
            a[i].x += v.x; a[i].y += v.y; a[i].z += v.z; a[i].w += v.w;
        }
        #pragma unroll
        for (int i = 0; i < 4; i++) {
            int d = (dw.y >> (8 * i)) & 255;
            float4 v = sr[d * 4 + ((q + (d >> 1)) & 3)];
            a[4 + i].x += v.x; a[4 + i].y += v.y;
            a[4 + i].z += v.z; a[4 + i].w += v.w;
        }

        // stage tree tt+1 (already in nv) into the other buffer
        if (tt + 1 < TPT) {
            int nb = cur ^ 1;
            float4* dr = s_r + nb * (Ln * 4);
            { int i = tid;       int d = i >> 2, k = i & 3; dr[d * 4 + ((k + (d >> 1)) & 3)] = nv0; }
            { int i = tid + 512; int d = i >> 2, k = i & 3; dr[d * 4 + ((k + (d >> 1)) & 3)] = nv1; }
            if (tid < BTILE / 4) s_du[nb * (BTILE / 4) + tid] = ndu;
        }
        // issue LDG for tree tt+2 (consumed by STS in the NEXT iteration)
        if (tt + 2 < TPT) {
            int t = tbase + tt + 2;
            const float4* rs = (const float4*)resp + (size_t)t * (Ln * Cn / 4);
            nv0 = rs[tid];
            nv1 = rs[tid + 512];
            if (tid < BTILE / 4)
                ndu = ((const unsigned*)(g_dec + (size_t)t * Bn + b0))[tid];
        }
        __syncthreads();
    }

    float4* pb = (float4*)g_part + ((size_t)blockIdx.y * Bn + b0 + sbase) * 4 + q;
    #pragma unroll
    for (int i = 0; i < 8; i++) pb[i * 4] = a[i];
}

// ---------------- kernel 4: reduce 16 partial tiles --------------------------
__global__ __launch_bounds__(256) void k_reduce(float* __restrict__ out) {
    int i = blockIdx.x * 256 + threadIdx.x;       // float2 index
    const float2* p = (const float2*)g_part;
    const size_t S = (size_t)Bn * Cn / 2;         // tile stride in float2

    float2 c[8];
    #pragma unroll
    for (int j = 0; j < 8; j++) c[j] = make_float2(0.f, 0.f);

    #pragma unroll
    for (int m = 0; m < TTILES / 8; m++) {
        #pragma unroll
        for (int j = 0; j < 8; j++) {
            float2 v = p[(size_t)(m * 8 + j) * S + i];
            c[j].x += v.x; c[j].y += v.y;
        }
    }
    float sx = ((c[0].x + c[1].x) + (c[2].x + c[3].x)) +
               ((c[4].x + c[5].x) + (c[6].x + c[7].x));
    float sy = ((c[0].y + c[1].y) + (c[2].y + c[3].y)) +
               ((c[4].y + c[5].y) + (c[6].y + c[7].y));
    const float sc = 1.0f / (float)Tn;
    ((float2*)out)[i] = make_float2(sx * sc, sy * sc);
}

// ---------------- launch -----------------------------------------------------
extern "C" void kernel_launch(void* const* d_in, const int* in_sizes, int n_in,
                              void* d_out, int out_size) {
    const float* x    = (const float*)d_in[0];   // (B, F)
    const float* fw   = (const float*)d_in[1];   // (T, D, F)
    const float* thr  = (const float*)d_in[2];   // (T, D)
    const float* resp = (const float*)d_in[3];   // (T, L, C)
    float* out = (float*)d_out;                  // (B, C)

    const int smem_dec = 32 * 513 * 4 + Tn * 16 + Tn * Dn * 4;     // 77952 B
    const int smem_acc = 2 * Ln * 4 * 16 + 2 * (BTILE / 4) * 4;    // 34816 B
    cudaFuncSetAttribute(k_decide, cudaFuncAttributeMaxDynamicSharedMemorySize,
                         smem_dec);
    cudaFuncSetAttribute(k_accum, cudaFuncAttributeMaxDynamicSharedMemorySize,
                         smem_acc);
    (void)in_sizes; (void)n_in; (void)out_size;

    k_argmax<<<(Tn * Dn) / 8, 256>>>(fw);                      // launch 1
    k_decide<<<Bn / 32, 512, smem_dec>>>(x, thr);              // launch 2
    k_tiny<<<1, 32>>>();                                       // launch 3 (shim)
    k_accum<<<dim3(BTILES, TTILES), 512, smem_acc>>>(resp);    // launch 4 <- ncu
    k_reduce<<<(Bn * Cn / 2) / 256, 256>>>(out);               // launch 5
}